// round 16
// baseline (speedup 1.0000x reference)
#include <cuda_runtime.h>

// Haar DWT2, single level.
// x: [8, 64, 512, 512] f32  ->  out: 4 subbands (ll, lh, hl, hh) concatenated,
// each [8, 64, 256, 256] f32.
//
// Best-known structure (150.4-151.2us kernel, DRAM=85%, 32 regs, occ-8):
// each thread reads a 2x8 input patch and writes one float4 per subband.
// Delta this round: Blackwell 256-bit loads (ld.global.cs.v8.f32 -> LDG.E.256)
// replace the 4x LDG.128 read path. Same bytes, same registers, half the LSU
// issue slots / L1tex wavefront entries on the read stream.

#define W_IN       512
#define SUBBAND_N  33554432u  // 512 * 256 * 256

__device__ __forceinline__ void ldg256_cs(const float* p, float r[8])
{
    asm volatile(
        "ld.global.cs.v8.f32 {%0,%1,%2,%3,%4,%5,%6,%7}, [%8];"
        : "=f"(r[0]), "=f"(r[1]), "=f"(r[2]), "=f"(r[3]),
          "=f"(r[4]), "=f"(r[5]), "=f"(r[6]), "=f"(r[7])
        : "l"(p));
}

__global__ void __launch_bounds__(256, 8)
haar_dwt2_kernel(const float* __restrict__ x, float* __restrict__ out)
{
    unsigned tid = blockIdx.x * blockDim.x + threadIdx.x;

    // tid = ((bc * 256) + i) * 64 + q   (all powers of two -> shifts)
    unsigned q  = tid & 63u;          // quad index along output width (j0 = 4*q)
    unsigned i  = (tid >> 6) & 255u;  // output row
    unsigned bc = tid >> 14;          // fused batch*channel index (0..511)

    // Input base: element ((bc*512 + 2*i) * 512 + 8*q)  (32 B aligned)
    unsigned in_base = ((bc << 9) + (i << 1)) * (unsigned)W_IN + (q << 3);

    // Two front-batched 256-bit loads (row 2i, row 2i+1)
    float r0[8];
    float r1[8];
    ldg256_cs(x + in_base, r0);
    ldg256_cs(x + in_base + W_IN, r1);

    // De-interleave columns: a = even cols (row 2i), b = odd cols (row 2i),
    //                        c = even cols (row 2i+1), d = odd cols (row 2i+1)
    float4 a = make_float4(r0[0], r0[2], r0[4], r0[6]);
    float4 b = make_float4(r0[1], r0[3], r0[5], r0[7]);
    float4 c = make_float4(r1[0], r1[2], r1[4], r1[6]);
    float4 d = make_float4(r1[1], r1[3], r1[5], r1[7]);

    const float s = 0.5f;

    float4 ll, lh, hl, hh;
    ll.x = (a.x + b.x + c.x + d.x) * s;
    ll.y = (a.y + b.y + c.y + d.y) * s;
    ll.z = (a.z + b.z + c.z + d.z) * s;
    ll.w = (a.w + b.w + c.w + d.w) * s;

    lh.x = (a.x + b.x - c.x - d.x) * s;
    lh.y = (a.y + b.y - c.y - d.y) * s;
    lh.z = (a.z + b.z - c.z - d.z) * s;
    lh.w = (a.w + b.w - c.w - d.w) * s;

    hl.x = (a.x - b.x + c.x - d.x) * s;
    hl.y = (a.y - b.y + c.y - d.y) * s;
    hl.z = (a.z - b.z + c.z - d.z) * s;
    hl.w = (a.w - b.w + c.w - d.w) * s;

    hh.x = (a.x - b.x - c.x + d.x) * s;
    hh.y = (a.y - b.y - c.y + d.y) * s;
    hh.z = (a.z - b.z - c.z + d.z) * s;
    hh.w = (a.w - b.w - c.w + d.w) * s;

    // Output element offset within a subband: ((bc*256 + i) * 256 + 4*q)
    unsigned out_off = (((bc << 8) + i) << 8) + (q << 2);

    __stcs((float4*)(out + out_off), ll);
    __stcs((float4*)(out + SUBBAND_N      + out_off), lh);
    __stcs((float4*)(out + 2u * SUBBAND_N + out_off), hl);
    __stcs((float4*)(out + 3u * SUBBAND_N + out_off), hh);
}

extern "C" void kernel_launch(void* const* d_in, const int* in_sizes, int n_in,
                              void* d_out, int out_size)
{
    const float* x = (const float*)d_in[0];
    float* out = (float*)d_out;

    // Total quads = 512 * 256 * 64 = 8,388,608 threads; 256 threads/block
    dim3 grid(8388608u / 256u);   // 32768 blocks
    dim3 block(256);
    haar_dwt2_kernel<<<grid, block>>>(x, out);
}